// round 4
// baseline (speedup 1.0000x reference)
#include <cuda_runtime.h>
#include <math.h>

// Problem constants
#define B_  32
#define T_  32
#define I_  256
#define H_  512
#define NH_ 4
#define HS_ 64
#define MS_ 2048
#define O_  256
// derived
#define KG_ 1024        // ctrl_in (512) + H (512)
#define NG_ 2048        // 4*H
#define NHP_ 516        // 4 heads * 129 used outputs
#define HPROW_ 2115     // HS + MS + 3

// ---------------- scratch (device globals; no allocation allowed) ----------------
__device__ float g_WgT[KG_ * NG_];            // [k][j*4+g]  8MB
__device__ float g_WhT[H_ * NHP_];            // [k][n*129+p] 1MB
__device__ float g_WoT[(H_ + NH_*HS_) * O_];  // [k][o]
__device__ float g_h[B_ * H_];
__device__ float g_c[B_ * H_];
__device__ float g_gates_part[4][B_][NG_];    // k-split partial gates
__device__ float g_hp_part[4][B_][NHP_];      // k-split partial head outputs
__device__ float g_scores[B_][8][MS_];        // raw scaled scores (rk0..3, wk0..3)
__device__ float g_stats[B_][8][8][2];        // [b][key][mchunk][{max,sumexp}]
__device__ float g_read_part[T_][8][B_][NH_*HS_]; // per-mchunk read partials
__device__ float g_hist_h[T_][B_][H_];
__device__ float g_mem[B_][MS_][HS_];         // 16.7MB

// ---------------- prep: weight re-layout + state zeroing ----------------
__global__ void k_prep(const float* __restrict__ W_ih, const float* __restrict__ W_hh,
                       const float* __restrict__ W_head, const float* __restrict__ W_out) {
    const int NWGT = KG_ * NG_;
    const int NWHT = H_ * NHP_;
    const int NWOT = (H_ + NH_*HS_) * O_;
    const int NZ   = B_*H_ + B_*H_ + B_*MS_*HS_;
    const int total = NWGT + NWHT + NWOT + NZ;
    for (int i = blockIdx.x * blockDim.x + threadIdx.x; i < total; i += gridDim.x * blockDim.x) {
        if (i < NWGT) {
            int k = i >> 11, np = i & 2047;          // NG_ = 2048
            int j = np >> 2, g = np & 3;
            int row = g * H_ + j;
            g_WgT[i] = (k < 512) ? W_ih[row * 512 + k] : W_hh[row * 512 + (k - 512)];
        } else if (i < NWGT + NWHT) {
            int r = i - NWGT;
            int k = r / NHP_, nn = r % NHP_;
            int n = nn / 129, p = nn % 129;
            g_WhT[r] = W_head[(n * HPROW_ + p) * 512 + k];
        } else if (i < NWGT + NWHT + NWOT) {
            int r = i - NWGT - NWHT;
            int k = r >> 8, o = r & 255;
            g_WoT[r] = W_out[o * (H_ + NH_*HS_) + k];
        } else {
            int r = i - NWGT - NWHT - NWOT;
            if (r < B_*H_)            g_h[r] = 0.f;
            else if (r < 2*B_*H_)     g_c[r - B_*H_] = 0.f;
            else                      (&g_mem[0][0][0])[r - 2*B_*H_] = 0.f;
        }
    }
}

// ---------------- gates GEMM (k-split partial): grid (32 j-chunks, 4 k-splits), 256 thr ----
__global__ void k_gates(const float* __restrict__ x, const float* __restrict__ b_ih,
                        const float* __restrict__ b_hh, int t) {
    const int jc = blockIdx.x, ks = blockIdx.y;
    const int tid = threadIdx.x;
    __shared__ float v_sh[32][128];
    const int b0 = tid >> 4;     // 0..15 (second batch half = b0+16)
    const int jj = tid & 15;
    const int j  = jc * 16 + jj;
    float4 acc0 = {0.f,0.f,0.f,0.f}, acc1 = {0.f,0.f,0.f,0.f};
    if (ks == 0) {  // bias added exactly once across k-splits
        acc0.x = b_ih[j]          + b_hh[j];
        acc0.y = b_ih[512 + j]    + b_hh[512 + j];
        acc0.z = b_ih[1024 + j]   + b_hh[1024 + j];
        acc0.w = b_ih[1536 + j]   + b_hh[1536 + j];
        acc1 = acc0;
    }
    for (int half = 0; half < 2; ++half) {
        const int kbase = ks * 256 + half * 128;
        __syncthreads();
        // load v tile: v[b][k] = [x_t | read_{t-1} | h_{t-1}]
        #pragma unroll
        for (int e = 0; e < 16; ++e) {
            int l = e * 256 + tid;
            int bb = l >> 7, kk = l & 127;
            int gk = kbase + kk;
            float vv;
            if (gk < 256) {
                vv = x[(bb * T_ + t) * I_ + gk];
            } else if (gk < 512) {
                if (t == 0) vv = 0.f;
                else {
                    int r = gk - 256;
                    const float* rp = &g_read_part[t - 1][0][bb][r];
                    vv = 0.f;
                    #pragma unroll
                    for (int mc = 0; mc < 8; ++mc) vv += rp[mc * (B_ * NH_ * HS_)];
                }
            } else {
                vv = g_h[bb * H_ + (gk - 512)];
            }
            v_sh[bb][kk] = vv;
        }
        __syncthreads();
        const float* wp = g_WgT + (size_t)kbase * NG_ + j * 4;
        #pragma unroll 8
        for (int kk = 0; kk < 128; ++kk) {
            float4 w = *(const float4*)(wp + (size_t)kk * NG_);
            float va = v_sh[b0][kk];
            float vb = v_sh[b0 + 16][kk];
            acc0.x += w.x * va; acc0.y += w.y * va; acc0.z += w.z * va; acc0.w += w.w * va;
            acc1.x += w.x * vb; acc1.y += w.y * vb; acc1.z += w.z * vb; acc1.w += w.w * vb;
        }
    }
    *(float4*)&g_gates_part[ks][b0][j * 4]      = acc0;
    *(float4*)&g_gates_part[ks][b0 + 16][j * 4] = acc1;
}

__device__ __forceinline__ float sigm_acc(float v) { return 1.f / (1.f + expf(-v)); }

// ---------------- LSTM elementwise + partial head GEMM: grid (8 b-groups, 4 k-splits), 512 thr ----
__global__ void k_lstm_head(int t) {
    const int bg = blockIdx.x, ks = blockIdx.y;
    const int tid = threadIdx.x;           // 512
    __shared__ float h_sh[4][128];
    {
        const int bl = tid >> 7, jl = tid & 127;
        const int b = bg * 4 + bl, j = ks * 128 + jl;
        float4 s = *(const float4*)&g_gates_part[0][b][j * 4];
        #pragma unroll
        for (int p = 1; p < 4; ++p) {
            float4 q = *(const float4*)&g_gates_part[p][b][j * 4];
            s.x += q.x; s.y += q.y; s.z += q.z; s.w += q.w;
        }
        float cold = g_c[b * H_ + j];
        float iv = sigm_acc(s.x);
        float fv = sigm_acc(s.y);
        float gv = tanhf(s.z);
        float ov = sigm_acc(s.w);
        float cn = fv * cold + iv * gv;
        float hn = ov * tanhf(cn);
        g_c[b * H_ + j] = cn;
        g_h[b * H_ + j] = hn;
        g_hist_h[t][b][j] = hn;
        h_sh[bl][jl] = hn;
    }
    __syncthreads();
    // head partial GEMM over k-range [ks*128, ks*128+128)
    #pragma unroll
    for (int e = 0; e < 5; ++e) {
        int idx = e * 512 + tid;
        if (idx < 4 * NHP_) {
            int bl = idx / NHP_, nn = idx % NHP_;
            const float* wp = g_WhT + ks * 128 * NHP_ + nn;
            const float* hp = h_sh[bl];
            float acc = 0.f;
            #pragma unroll 8
            for (int k = 0; k < 128; ++k) acc += hp[k] * wp[k * NHP_];
            g_hp_part[ks][bg * 4 + bl][nn] = acc;
        }
    }
}

// ---------------- attention scores + chunk softmax stats: grid (32 b, 8 m-chunks), 256 thr ----
__global__ void k_scores(const float* __restrict__ b_head, int /*t*/) {
    const int b = blockIdx.x, mc = blockIdx.y;
    const int tid = threadIdx.x;
    __shared__ float key_sh[8][64];     // scaled: rk 0..3, wk 4..7
    __shared__ float sc_sh[8][256];
    #pragma unroll
    for (int e = 0; e < 2; ++e) {
        int i = e * 256 + tid;
        int key = i >> 6, h = i & 63;
        int n = key & 3;
        int p = (key < 4) ? h : 64 + h;
        float v = b_head[n * HPROW_ + p];
        #pragma unroll
        for (int ps = 0; ps < 4; ++ps) v += g_hp_part[ps][b][n * 129 + p];
        key_sh[key][h] = v * 0.125f;    // fold 1/sqrt(HS)
    }
    __syncthreads();
    const int w = tid >> 5, l = tid & 31;
    const int msub = l >> 3, hb = (l & 7) * 8;
    float kreg[8][8];
    #pragma unroll
    for (int key = 0; key < 8; ++key) {
        float4 a = *(const float4*)&key_sh[key][hb];
        float4 c = *(const float4*)&key_sh[key][hb + 4];
        kreg[key][0]=a.x; kreg[key][1]=a.y; kreg[key][2]=a.z; kreg[key][3]=a.w;
        kreg[key][4]=c.x; kreg[key][5]=c.y; kreg[key][6]=c.z; kreg[key][7]=c.w;
    }
    #pragma unroll
    for (int it = 0; it < 8; ++it) {
        int ml = it * 32 + w * 4 + msub;
        int m = mc * 256 + ml;
        const float* mp = &g_mem[b][m][hb];
        float4 a = *(const float4*)mp;
        float4 c = *(const float4*)(mp + 4);
        float mv[8] = {a.x, a.y, a.z, a.w, c.x, c.y, c.z, c.w};
        #pragma unroll
        for (int key = 0; key < 8; ++key) {
            float d = 0.f;
            #pragma unroll
            for (int q = 0; q < 8; ++q) d += kreg[key][q] * mv[q];
            d += __shfl_xor_sync(0xffffffffu, d, 1);
            d += __shfl_xor_sync(0xffffffffu, d, 2);
            d += __shfl_xor_sync(0xffffffffu, d, 4);
            if ((l & 7) == 0) sc_sh[key][ml] = d;
        }
    }
    __syncthreads();
    // coalesced score dump for the apply kernel
    #pragma unroll
    for (int e = 0; e < 8; ++e) {
        int i = e * 256 + tid;
        int key = i >> 8, ml = i & 255;
        g_scores[b][key][mc * 256 + ml] = sc_sh[key][ml];
    }
    // chunk softmax stats: warp w handles key w (8 warps == 8 keys)
    float mx = -1e30f;
    for (int i = l; i < 256; i += 32) mx = fmaxf(mx, sc_sh[w][i]);
    #pragma unroll
    for (int s = 16; s; s >>= 1) mx = fmaxf(mx, __shfl_xor_sync(0xffffffffu, mx, s));
    float se = 0.f;
    for (int i = l; i < 256; i += 32) se += __expf(sc_sh[w][i] - mx);
    #pragma unroll
    for (int s = 16; s; s >>= 1) se += __shfl_xor_sync(0xffffffffu, se, s);
    if (l == 0) { g_stats[b][w][mc][0] = mx; g_stats[b][w][mc][1] = se; }
}

// ---------------- read accumulation + memory update: grid (32 b, 8 m-chunks), 256 thr ----
__global__ void k_apply(const float* __restrict__ b_head, int t) {
    const int b = blockIdx.x, mc = blockIdx.y;
    const int tid = threadIdx.x;
    __shared__ float w_sh[8][256];
    __shared__ float sk_sh[4][64];       // ws[n] * write_keys[n][h]
    __shared__ float ws_sh[4];
    __shared__ float gm_sh[8], inv_sh[8];
    __shared__ float racc_sh[8][4][64];
    // phase 0: global softmax stats (tid 0..7) + write strength (tid 8..11)
    if (tid < 8) {
        int key = tid;
        float gm = -1e30f;
        #pragma unroll
        for (int c = 0; c < 8; ++c) gm = fmaxf(gm, g_stats[b][key][c][0]);
        float s = 0.f;
        #pragma unroll
        for (int c = 0; c < 8; ++c) s += g_stats[b][key][c][1] * __expf(g_stats[b][key][c][0] - gm);
        gm_sh[key] = gm; inv_sh[key] = 1.f / s;
    } else if (tid < 12) {
        int n = tid - 8;
        float v = b_head[n * HPROW_ + 128];
        #pragma unroll
        for (int ps = 0; ps < 4; ++ps) v += g_hp_part[ps][b][n * 129 + 128];
        ws_sh[n] = sigm_acc(v);
    }
    __syncthreads();
    // phase 1: sk = ws * write_keys (raw), and weights from raw scores
    {
        int n = tid >> 6, h = tid & 63;
        float v = b_head[n * HPROW_ + 64 + h];
        #pragma unroll
        for (int ps = 0; ps < 4; ++ps) v += g_hp_part[ps][b][n * 129 + 64 + h];
        sk_sh[n][h] = v * ws_sh[n];
    }
    #pragma unroll
    for (int e = 0; e < 8; ++e) {
        int i = e * 256 + tid;
        int key = i >> 8, ml = i & 255;
        w_sh[key][ml] = __expf(g_scores[b][key][mc * 256 + ml] - gm_sh[key]) * inv_sh[key];
    }
    __syncthreads();
    const int w = tid >> 5, l = tid & 31;
    const int msub = l >> 3, hb = (l & 7) * 8;
    float skreg[4][8];
    #pragma unroll
    for (int n = 0; n < 4; ++n) {
        float4 a = *(const float4*)&sk_sh[n][hb];
        float4 c = *(const float4*)&sk_sh[n][hb + 4];
        skreg[n][0]=a.x; skreg[n][1]=a.y; skreg[n][2]=a.z; skreg[n][3]=a.w;
        skreg[n][4]=c.x; skreg[n][5]=c.y; skreg[n][6]=c.z; skreg[n][7]=c.w;
    }
    float racc[4][8];
    #pragma unroll
    for (int n = 0; n < 4; ++n)
        #pragma unroll
        for (int q = 0; q < 8; ++q) racc[n][q] = 0.f;
    #pragma unroll
    for (int it = 0; it < 8; ++it) {
        int ml = it * 32 + w * 4 + msub;
        int m = mc * 256 + ml;
        float* mp = &g_mem[b][m][hb];
        float4 a = *(const float4*)mp;
        float4 c = *(const float4*)(mp + 4);
        float mv[8] = {a.x, a.y, a.z, a.w, c.x, c.y, c.z, c.w};
        float rw[4], ww[4];
        #pragma unroll
        for (int n = 0; n < 4; ++n) { rw[n] = w_sh[n][ml]; ww[n] = w_sh[4 + n][ml]; }
        // read accumulation uses OLD mem
        #pragma unroll
        for (int n = 0; n < 4; ++n)
            #pragma unroll
            for (int q = 0; q < 8; ++q) racc[n][q] += rw[n] * mv[q];
        // memory update
        #pragma unroll
        for (int q = 0; q < 8; ++q) {
            mv[q] += ww[0]*skreg[0][q] + ww[1]*skreg[1][q] + ww[2]*skreg[2][q] + ww[3]*skreg[3][q];
        }
        a.x=mv[0]; a.y=mv[1]; a.z=mv[2]; a.w=mv[3];
        c.x=mv[4]; c.y=mv[5]; c.z=mv[6]; c.w=mv[7];
        *(float4*)mp = a;
        *(float4*)(mp + 4) = c;
    }
    // reduce racc across the 4 m-subgroups (lanes xor 8,16) — deterministic
    #pragma unroll
    for (int n = 0; n < 4; ++n)
        #pragma unroll
        for (int q = 0; q < 8; ++q) {
            racc[n][q] += __shfl_xor_sync(0xffffffffu, racc[n][q], 8);
            racc[n][q] += __shfl_xor_sync(0xffffffffu, racc[n][q], 16);
        }
    if (l < 8) {
        #pragma unroll
        for (int n = 0; n < 4; ++n)
            #pragma unroll
            for (int q = 0; q < 8; ++q) racc_sh[w][n][hb + q] = racc[n][q];
    }
    __syncthreads();
    {
        int n = tid >> 6, h = tid & 63;
        float s = 0.f;
        #pragma unroll
        for (int wr = 0; wr < 8; ++wr) s += racc_sh[wr][n][h];
        g_read_part[t][mc][b][n * 64 + h] = s;
    }
}

// ---------------- final output GEMM: outputs[b][t][o]; grid (32 m-chunks, 4 n-chunks), 256 thr ----
__global__ void k_out(const float* __restrict__ b_out, float* __restrict__ out) {
    const int m0 = blockIdx.x * 32, nc = blockIdx.y;
    const int tid = threadIdx.x;
    __shared__ float a_sh[32][64];
    const int n_l = tid & 63, mg = tid >> 6;
    const int n = nc * 64 + n_l;
    float acc[8];
    #pragma unroll
    for (int r = 0; r < 8; ++r) acc[r] = 0.f;
    for (int kt = 0; kt < 12; ++kt) {
        __syncthreads();
        #pragma unroll
        for (int e = 0; e < 8; ++e) {
            int lidx = e * 256 + tid;
            int mrow = lidx >> 6, kk = lidx & 63;
            int m = m0 + mrow;
            int ts = m >> 5, bb = m & 31;
            int gk = kt * 64 + kk;
            float v;
            if (gk < 512) v = g_hist_h[ts][bb][gk];
            else {
                int r = gk - 512;
                v = 0.f;
                #pragma unroll
                for (int c = 0; c < 8; ++c) v += g_read_part[ts][c][bb][r];
            }
            a_sh[mrow][kk] = v;
        }
        __syncthreads();
        #pragma unroll 4
        for (int kk = 0; kk < 64; ++kk) {
            float wv = g_WoT[(kt * 64 + kk) * O_ + n];
            #pragma unroll
            for (int r = 0; r < 8; ++r) acc[r] += a_sh[mg * 8 + r][kk] * wv;
        }
    }
    float bo = b_out[n];
    #pragma unroll
    for (int r = 0; r < 8; ++r) {
        int m = m0 + mg * 8 + r;
        int ts = m >> 5, bb = m & 31;
        out[(bb * T_ + ts) * O_ + n] = acc[r] + bo;
    }
}

// ---------------- final state copy: mem, h, c into d_out ----------------
__global__ void k_final(float* __restrict__ out) {
    const int OUT_N = B_ * T_ * O_;            // 262144
    const int NMEM  = B_ * MS_ * HS_;          // 4194304
    const int total = NMEM + 2 * B_ * H_;
    for (int i = blockIdx.x * blockDim.x + threadIdx.x; i < total; i += gridDim.x * blockDim.x) {
        if (i < NMEM)                 out[OUT_N + i] = (&g_mem[0][0][0])[i];
        else if (i < NMEM + B_ * H_)  out[OUT_N + i] = g_h[i - NMEM];
        else                          out[OUT_N + i] = g_c[i - NMEM - B_ * H_];
    }
}

extern "C" void kernel_launch(void* const* d_in, const int* in_sizes, int n_in,
                              void* d_out, int out_size) {
    const float* x      = (const float*)d_in[0];
    const float* W_ih   = (const float*)d_in[1];
    const float* W_hh   = (const float*)d_in[2];
    const float* b_ih   = (const float*)d_in[3];
    const float* b_hh   = (const float*)d_in[4];
    const float* W_head = (const float*)d_in[5];
    const float* b_head = (const float*)d_in[6];
    const float* W_out  = (const float*)d_in[7];
    const float* b_out  = (const float*)d_in[8];
    float* out = (float*)d_out;

    k_prep<<<1024, 256>>>(W_ih, W_hh, W_head, W_out);
    for (int t = 0; t < T_; ++t) {
        k_gates<<<dim3(32, 4), 256>>>(x, b_ih, b_hh, t);
        k_lstm_head<<<dim3(8, 4), 512>>>(t);
        k_scores<<<dim3(32, 8), 256>>>(b_head, t);
        k_apply<<<dim3(32, 8), 256>>>(b_head, t);
    }
    k_out<<<dim3(32, 4), 256>>>(b_out, out);
    k_final<<<2048, 256>>>(out);
}

// round 5
// speedup vs baseline: 1.9815x; 1.9815x over previous
#include <cuda_runtime.h>
#include <math.h>

// Problem constants
#define B_  32
#define T_  32
#define I_  256
#define H_  512
#define NH_ 4
#define HS_ 64
#define MS_ 2048
#define O_  256
// derived
#define KG_ 1024        // ctrl_in (512) + H (512)
#define NG_ 2048        // 4*H, gate col index n = g*512 + j
#define NHP_ 516        // 4 heads * 129 used head outputs
#define HPROW_ 2115     // HS + MS + 3
#define NBLK 128
#define NBAR (4*T_)

// ---------------- scratch (device globals; no allocation allowed) ----------------
__device__ float g_WgT[KG_*NG_];              // [k][n]  8MB   (n = g*512+j)
__device__ float g_WhT[H_*NHP_];              // [k][n*129+p]  1MB
__device__ float g_WoT[(H_+NH_*HS_)*O_];      // [k][o]
__device__ float g_h[B_*H_];
__device__ float g_c[B_*H_];
__device__ float g_gates_part[8][B_][NG_];    // k-split (8) partial gates
__device__ float g_hp_part[16][B_][NHP_];     // k-split (16) partial head outputs
__device__ float2 g_stats[B_][8][4];          // [b][key][mq] = {chunk max, chunk sumexp}
__device__ float g_read_part[T_][4][B_][NH_*HS_]; // per-mq read partials
__device__ float g_hist_h[T_][B_][H_];
__device__ float g_mem[B_][MS_][HS_];         // 16.7MB
__device__ int   g_bar[NBAR];

__device__ __forceinline__ float sigm_acc(float v) { return 1.f / (1.f + expf(-v)); }

// ---------------- software grid barrier (monotonic index, no reset) ----------------
__device__ __forceinline__ void gridbar(int idx) {
    __syncthreads();
    if (threadIdx.x == 0) {
        __threadfence();
        atomicAdd(&g_bar[idx], 1);
        while (*((volatile int*)&g_bar[idx]) < NBLK) { __nanosleep(32); }
        __threadfence();
    }
    __syncthreads();
}

// ---------------- prep kernels ----------------
__global__ void k_zero() {
    const int NMEM = B_*MS_*HS_;
    const int total = NMEM + 2*B_*H_ + NBAR;
    for (int i = blockIdx.x*blockDim.x+threadIdx.x; i < total; i += gridDim.x*blockDim.x) {
        if (i < NMEM)                   (&g_mem[0][0][0])[i] = 0.f;
        else if (i < NMEM + B_*H_)      g_h[i - NMEM] = 0.f;
        else if (i < NMEM + 2*B_*H_)    g_c[i - NMEM - B_*H_] = 0.f;
        else                            g_bar[i - NMEM - 2*B_*H_] = 0;
    }
}

// WgT[k][n] = A[n][k] where A = [W_ih | W_hh] rows (n is already the gate-col index).
__global__ void k_trA(const float* __restrict__ W_ih, const float* __restrict__ W_hh) {
    __shared__ float tile[32][33];
    const int bx = blockIdx.x * 32;   // k
    const int by = blockIdx.y * 32;   // n (gate rows)
    const int tx = threadIdx.x, ty = threadIdx.y;
    #pragma unroll
    for (int i = 0; i < 32; i += 8) {
        int row = by + ty + i, k = bx + tx;
        float v = (k < 512) ? W_ih[row*512 + k] : W_hh[row*512 + (k - 512)];
        tile[ty + i][tx] = v;
    }
    __syncthreads();
    #pragma unroll
    for (int i = 0; i < 32; i += 8) {
        int k = bx + ty + i, row = by + tx;
        g_WgT[(size_t)k * NG_ + row] = tile[tx][ty + i];
    }
}

// WhT[k][r] with r = n*129 + p over used head rows
__global__ void k_trH(const float* __restrict__ W_head) {
    __shared__ float tile[32][33];
    const int bx = blockIdx.x * 32;   // k (512)
    const int by = blockIdx.y * 32;   // r (516, guard)
    const int tx = threadIdx.x, ty = threadIdx.y;
    #pragma unroll
    for (int i = 0; i < 32; i += 8) {
        int r = by + ty + i, k = bx + tx;
        float v = 0.f;
        if (r < NHP_) {
            int n = r / 129, p = r % 129;
            v = W_head[(size_t)(n * HPROW_ + p) * 512 + k];
        }
        tile[ty + i][tx] = v;
    }
    __syncthreads();
    #pragma unroll
    for (int i = 0; i < 32; i += 8) {
        int k = bx + ty + i, r = by + tx;
        if (r < NHP_) g_WhT[(size_t)k * NHP_ + r] = tile[tx][ty + i];
    }
}

// WoT[k][o] = W_out[o][k]
__global__ void k_trO(const float* __restrict__ W_out) {
    __shared__ float tile[32][33];
    const int bx = blockIdx.x * 32;   // k (768)
    const int by = blockIdx.y * 32;   // o (256)
    const int tx = threadIdx.x, ty = threadIdx.y;
    #pragma unroll
    for (int i = 0; i < 32; i += 8) {
        int o = by + ty + i, k = bx + tx;
        tile[ty + i][tx] = W_out[o * (H_ + NH_*HS_) + k];
    }
    __syncthreads();
    #pragma unroll
    for (int i = 0; i < 32; i += 8) {
        int k = bx + ty + i, o = by + tx;
        g_WoT[(size_t)k * O_ + o] = tile[tx][ty + i];
    }
}

// ---------------- the persistent recurrence kernel ----------------
struct SmGates { float v[128][32]; float w[32][128]; };
struct SmP2    { float h[4][32]; };
struct SmAttn  {
    float key[8][64];
    float stat[8][256];
    float gm[8], inv[8], ws[4];
    float sk[4][64];
    float wsm[8][512];
    float racc[8][4][64];
};
union SmU { SmGates g; SmP2 p2; SmAttn a; };

__global__ __launch_bounds__(256, 1)
void k_steps(const float* __restrict__ x, const float* __restrict__ b_ih,
             const float* __restrict__ b_hh, const float* __restrict__ b_head) {
    __shared__ SmU sm;
    const int bid = blockIdx.x, tid = threadIdx.x;

    // P1 partition
    const int nc = bid >> 3, ksg = bid & 7;
    const int n0 = nc * 128, k0g = ksg * 128;
    const int n4 = tid & 31, bq = tid >> 5;
    const int b0v = bq * 4;
    // P2 partition
    const int bq2 = bid >> 4, ks2 = bid & 15;
    const int b02 = bq2 * 4, j0 = ks2 * 32;
    // P3/P4 partition
    const int ab = bid >> 2, mq = bid & 3;
    const int m0 = mq * 512;

    for (int t = 0; t < T_; ++t) {
        // ================= P1: gates GEMM (partials over 8 k-slices) =================
        {
            float acc[4][4];
            #pragma unroll
            for (int bi = 0; bi < 4; ++bi)
                #pragma unroll
                for (int ni = 0; ni < 4; ++ni) acc[bi][ni] = 0.f;
            // load v tile [128k][32b]
            #pragma unroll
            for (int e = 0; e < 16; ++e) {
                int idx = e * 256 + tid;
                int kk = idx >> 5, bb = idx & 31;
                int gk = k0g + kk;
                float vv;
                if (gk < 256) {
                    vv = x[(bb * T_ + t) * I_ + gk];
                } else if (gk < 512) {
                    if (t == 0) vv = 0.f;
                    else {
                        int r = gk - 256;
                        vv = g_read_part[t-1][0][bb][r] + g_read_part[t-1][1][bb][r]
                           + g_read_part[t-1][2][bb][r] + g_read_part[t-1][3][bb][r];
                    }
                } else {
                    vv = __ldcg(&g_h[bb * H_ + (gk - 512)]);
                }
                sm.g.v[kk][bb] = vv;
            }
            for (int c = 0; c < 4; ++c) {
                __syncthreads();
                #pragma unroll
                for (int e = 0; e < 4; ++e) {
                    int lin = e * 1024 + tid * 4;
                    int row = lin >> 7, col = lin & 127;
                    *(float4*)&sm.g.w[row][col] =
                        *(const float4*)&g_WgT[(size_t)(k0g + c*32 + row) * NG_ + n0 + col];
                }
                __syncthreads();
                #pragma unroll
                for (int kk = 0; kk < 32; ++kk) {
                    float4 v4 = *(const float4*)&sm.g.v[c*32 + kk][b0v];
                    float4 w4 = *(const float4*)&sm.g.w[kk][n4 * 4];
                    acc[0][0] += v4.x*w4.x; acc[0][1] += v4.x*w4.y; acc[0][2] += v4.x*w4.z; acc[0][3] += v4.x*w4.w;
                    acc[1][0] += v4.y*w4.x; acc[1][1] += v4.y*w4.y; acc[1][2] += v4.y*w4.z; acc[1][3] += v4.y*w4.w;
                    acc[2][0] += v4.z*w4.x; acc[2][1] += v4.z*w4.y; acc[2][2] += v4.z*w4.z; acc[2][3] += v4.z*w4.w;
                    acc[3][0] += v4.w*w4.x; acc[3][1] += v4.w*w4.y; acc[3][2] += v4.w*w4.z; acc[3][3] += v4.w*w4.w;
                }
            }
            const int col0 = n0 + n4 * 4;
            if (ksg == 0) {
                float4 bi4 = make_float4(b_ih[col0] + b_hh[col0],
                                         b_ih[col0+1] + b_hh[col0+1],
                                         b_ih[col0+2] + b_hh[col0+2],
                                         b_ih[col0+3] + b_hh[col0+3]);
                #pragma unroll
                for (int bi = 0; bi < 4; ++bi) {
                    acc[bi][0] += bi4.x; acc[bi][1] += bi4.y; acc[bi][2] += bi4.z; acc[bi][3] += bi4.w;
                }
            }
            #pragma unroll
            for (int bi = 0; bi < 4; ++bi) {
                float4 o4 = make_float4(acc[bi][0], acc[bi][1], acc[bi][2], acc[bi][3]);
                *(float4*)&g_gates_part[ksg][b0v + bi][col0] = o4;
            }
        }
        gridbar(4*t + 0);

        // ================= P2: LSTM elementwise + partial head GEMM =================
        {
            if (tid < 128) {
                int bi = tid >> 5, jj = tid & 31;
                int b = b02 + bi, j = j0 + jj;
                float gi = 0.f, gf = 0.f, gg = 0.f, go = 0.f;
                #pragma unroll
                for (int p = 0; p < 8; ++p) {
                    gi += __ldcg(&g_gates_part[p][b][j]);
                    gf += __ldcg(&g_gates_part[p][b][512 + j]);
                    gg += __ldcg(&g_gates_part[p][b][1024 + j]);
                    go += __ldcg(&g_gates_part[p][b][1536 + j]);
                }
                float cold = g_c[b * H_ + j];
                float iv = sigm_acc(gi), fv = sigm_acc(gf);
                float gv = tanhf(gg),   ov = sigm_acc(go);
                float cn = fv * cold + iv * gv;
                float hn = ov * tanhf(cn);
                g_c[b * H_ + j] = cn;
                g_h[b * H_ + j] = hn;
                g_hist_h[t][b][j] = hn;
                sm.p2.h[bi][jj] = hn;
            }
            __syncthreads();
            #pragma unroll
            for (int e = 0; e < 3; ++e) {
                int nn = tid + e * 256;
                if (nn < NHP_) {
                    float a0 = 0.f, a1 = 0.f, a2 = 0.f, a3 = 0.f;
                    #pragma unroll
                    for (int k = 0; k < 32; ++k) {
                        float w = g_WhT[(size_t)(j0 + k) * NHP_ + nn];
                        a0 += sm.p2.h[0][k] * w;
                        a1 += sm.p2.h[1][k] * w;
                        a2 += sm.p2.h[2][k] * w;
                        a3 += sm.p2.h[3][k] * w;
                    }
                    g_hp_part[ks2][b02 + 0][nn] = a0;
                    g_hp_part[ks2][b02 + 1][nn] = a1;
                    g_hp_part[ks2][b02 + 2][nn] = a2;
                    g_hp_part[ks2][b02 + 3][nn] = a3;
                }
            }
        }
        gridbar(4*t + 1);

        // ================= P3: attention scores (kept in registers) =================
        float s[2][8];
        {
            #pragma unroll
            for (int e = 0; e < 2; ++e) {
                int idx = e * 256 + tid;
                int key = idx >> 6, h = idx & 63;
                int n = key & 3;
                int p = (key < 4) ? h : 64 + h;
                float v = b_head[n * HPROW_ + p];
                #pragma unroll
                for (int ps = 0; ps < 16; ++ps) v += __ldcg(&g_hp_part[ps][ab][n * 129 + p]);
                sm.a.key[key][h] = v * 0.125f;   // fold 1/sqrt(HS)
            }
            __syncthreads();
            #pragma unroll
            for (int ms = 0; ms < 2; ++ms)
                #pragma unroll
                for (int key = 0; key < 8; ++key) s[ms][key] = 0.f;
            #pragma unroll
            for (int ms = 0; ms < 2; ++ms) {
                const int m = m0 + tid * 2 + ms;
                const float4* mp = (const float4*)&g_mem[ab][m][0];
                float4 r[16];
                #pragma unroll
                for (int i = 0; i < 16; ++i) r[i] = mp[i];
                #pragma unroll
                for (int hc = 0; hc < 16; ++hc) {
                    float4 mv = r[hc];
                    #pragma unroll
                    for (int key = 0; key < 8; ++key) {
                        float4 kq = *(const float4*)&sm.a.key[key][hc * 4];
                        s[ms][key] += kq.x*mv.x + kq.y*mv.y + kq.z*mv.z + kq.w*mv.w;
                    }
                }
            }
            // chunk stats: max
            #pragma unroll
            for (int key = 0; key < 8; ++key)
                sm.a.stat[key][tid] = fmaxf(s[0][key], s[1][key]);
            __syncthreads();
            {
                const int w = tid >> 5, l = tid & 31;
                float mx = -1e30f;
                for (int i = l; i < 256; i += 32) mx = fmaxf(mx, sm.a.stat[w][i]);
                #pragma unroll
                for (int sh = 16; sh; sh >>= 1) mx = fmaxf(mx, __shfl_xor_sync(0xffffffffu, mx, sh));
                if (l == 0) sm.a.gm[w] = mx;
            }
            __syncthreads();
            #pragma unroll
            for (int key = 0; key < 8; ++key)
                sm.a.stat[key][tid] = __expf(s[0][key] - sm.a.gm[key]) + __expf(s[1][key] - sm.a.gm[key]);
            __syncthreads();
            {
                const int w = tid >> 5, l = tid & 31;
                float se = 0.f;
                for (int i = l; i < 256; i += 32) se += sm.a.stat[w][i];
                #pragma unroll
                for (int sh = 16; sh; sh >>= 1) se += __shfl_xor_sync(0xffffffffu, se, sh);
                if (l == 0) g_stats[ab][w][mq] = make_float2(sm.a.gm[w], se);
            }
        }
        gridbar(4*t + 2);

        // ================= P4: softmax apply, read accumulate, memory update =================
        {
            if (tid < 8) {
                float2 st0 = __ldcg(&g_stats[ab][tid][0]);
                float2 st1 = __ldcg(&g_stats[ab][tid][1]);
                float2 st2 = __ldcg(&g_stats[ab][tid][2]);
                float2 st3 = __ldcg(&g_stats[ab][tid][3]);
                float gm = fmaxf(fmaxf(st0.x, st1.x), fmaxf(st2.x, st3.x));
                float ssum = st0.y * __expf(st0.x - gm) + st1.y * __expf(st1.x - gm)
                           + st2.y * __expf(st2.x - gm) + st3.y * __expf(st3.x - gm);
                sm.a.gm[tid] = gm; sm.a.inv[tid] = 1.f / ssum;
            } else if (tid < 12) {
                int n = tid - 8;
                float v = b_head[n * HPROW_ + 128];
                #pragma unroll
                for (int ps = 0; ps < 16; ++ps) v += __ldcg(&g_hp_part[ps][ab][n * 129 + 128]);
                sm.a.ws[n] = sigm_acc(v);
            }
            __syncthreads();
            {
                int n = tid >> 6, h = tid & 63;
                float v = b_head[n * HPROW_ + 64 + h];
                #pragma unroll
                for (int ps = 0; ps < 16; ++ps) v += __ldcg(&g_hp_part[ps][ab][n * 129 + 64 + h]);
                sm.a.sk[n][h] = v * sm.a.ws[n];
            }
            #pragma unroll
            for (int ms = 0; ms < 2; ++ms)
                #pragma unroll
                for (int key = 0; key < 8; ++key)
                    sm.a.wsm[key][tid * 2 + ms] = __expf(s[ms][key] - sm.a.gm[key]) * sm.a.inv[key];
            __syncthreads();

            const int w = tid >> 5, l = tid & 31;
            const int msub = l >> 3, hb = (l & 7) * 8;
            float skreg[4][8];
            #pragma unroll
            for (int n = 0; n < 4; ++n) {
                float4 a4 = *(const float4*)&sm.a.sk[n][hb];
                float4 c4 = *(const float4*)&sm.a.sk[n][hb + 4];
                skreg[n][0]=a4.x; skreg[n][1]=a4.y; skreg[n][2]=a4.z; skreg[n][3]=a4.w;
                skreg[n][4]=c4.x; skreg[n][5]=c4.y; skreg[n][6]=c4.z; skreg[n][7]=c4.w;
            }
            float racc[4][8];
            #pragma unroll
            for (int n = 0; n < 4; ++n)
                #pragma unroll
                for (int q = 0; q < 8; ++q) racc[n][q] = 0.f;
            #pragma unroll
            for (int it = 0; it < 16; ++it) {
                int ml = it * 32 + w * 4 + msub;
                int m = m0 + ml;
                float* mp = &g_mem[ab][m][hb];
                float4 a4 = *(const float4*)mp;
                float4 c4 = *(const float4*)(mp + 4);
                float mv[8] = {a4.x, a4.y, a4.z, a4.w, c4.x, c4.y, c4.z, c4.w};
                float rw[4], ww[4];
                #pragma unroll
                for (int n = 0; n < 4; ++n) { rw[n] = sm.a.wsm[n][ml]; ww[n] = sm.a.wsm[4 + n][ml]; }
                #pragma unroll
                for (int n = 0; n < 4; ++n)
                    #pragma unroll
                    for (int q = 0; q < 8; ++q) racc[n][q] += rw[n] * mv[q];
                #pragma unroll
                for (int q = 0; q < 8; ++q)
                    mv[q] += ww[0]*skreg[0][q] + ww[1]*skreg[1][q] + ww[2]*skreg[2][q] + ww[3]*skreg[3][q];
                a4.x=mv[0]; a4.y=mv[1]; a4.z=mv[2]; a4.w=mv[3];
                c4.x=mv[4]; c4.y=mv[5]; c4.z=mv[6]; c4.w=mv[7];
                *(float4*)mp = a4;
                *(float4*)(mp + 4) = c4;
            }
            #pragma unroll
            for (int n = 0; n < 4; ++n)
                #pragma unroll
                for (int q = 0; q < 8; ++q) {
                    racc[n][q] += __shfl_xor_sync(0xffffffffu, racc[n][q], 8);
                    racc[n][q] += __shfl_xor_sync(0xffffffffu, racc[n][q], 16);
                }
            if (l < 8) {
                #pragma unroll
                for (int n = 0; n < 4; ++n)
                    #pragma unroll
                    for (int q = 0; q < 8; ++q) sm.a.racc[w][n][hb + q] = racc[n][q];
            }
            __syncthreads();
            {
                int n = tid >> 6, h = tid & 63;
                float ssum = 0.f;
                #pragma unroll
                for (int wr = 0; wr < 8; ++wr) ssum += sm.a.racc[wr][n][h];
                g_read_part[t][mq][ab][n * 64 + h] = ssum;
            }
        }
        gridbar(4*t + 3);
    }
}

// ---------------- final output GEMM: outputs[b][t][o] ----------------
__global__ void k_out(const float* __restrict__ b_out, float* __restrict__ out) {
    const int m0 = blockIdx.x * 32, nc = blockIdx.y;
    const int tid = threadIdx.x;
    __shared__ float a_sh[32][64];
    const int n_l = tid & 63, mg = tid >> 6;
    const int n = nc * 64 + n_l;
    float acc[8];
    #pragma unroll
    for (int r = 0; r < 8; ++r) acc[r] = 0.f;
    for (int kt = 0; kt < 12; ++kt) {
        __syncthreads();
        #pragma unroll
        for (int e = 0; e < 8; ++e) {
            int lidx = e * 256 + tid;
            int mrow = lidx >> 6, kk = lidx & 63;
            int m = m0 + mrow;
            int ts = m >> 5, bb = m & 31;
            int gk = kt * 64 + kk;
            float v;
            if (gk < 512) v = g_hist_h[ts][bb][gk];
            else {
                int r = gk - 512;
                v = g_read_part[ts][0][bb][r] + g_read_part[ts][1][bb][r]
                  + g_read_part[ts][2][bb][r] + g_read_part[ts][3][bb][r];
            }
            a_sh[mrow][kk] = v;
        }
        __syncthreads();
        #pragma unroll 4
        for (int kk = 0; kk < 64; ++kk) {
            float wv = g_WoT[(kt * 64 + kk) * O_ + n];
            #pragma unroll
            for (int r = 0; r < 8; ++r) acc[r] += a_sh[mg * 8 + r][kk] * wv;
        }
    }
    float bo = b_out[n];
    #pragma unroll
    for (int r = 0; r < 8; ++r) {
        int m = m0 + mg * 8 + r;
        int ts = m >> 5, bb = m & 31;
        out[(bb * T_ + ts) * O_ + n] = acc[r] + bo;
    }
}

// ---------------- final state copy: mem, h, c into d_out ----------------
__global__ void k_final(float* __restrict__ out) {
    const int OUT_N = B_ * T_ * O_;            // 262144
    const int NMEM  = B_ * MS_ * HS_;          // 4194304
    const int total = NMEM + 2 * B_ * H_;
    for (int i = blockIdx.x * blockDim.x + threadIdx.x; i < total; i += gridDim.x * blockDim.x) {
        if (i < NMEM)                 out[OUT_N + i] = (&g_mem[0][0][0])[i];
        else if (i < NMEM + B_ * H_)  out[OUT_N + i] = g_h[i - NMEM];
        else                          out[OUT_N + i] = g_c[i - NMEM - B_ * H_];
    }
}

extern "C" void kernel_launch(void* const* d_in, const int* in_sizes, int n_in,
                              void* d_out, int out_size) {
    const float* x      = (const float*)d_in[0];
    const float* W_ih   = (const float*)d_in[1];
    const float* W_hh   = (const float*)d_in[2];
    const float* b_ih   = (const float*)d_in[3];
    const float* b_hh   = (const float*)d_in[4];
    const float* W_head = (const float*)d_in[5];
    const float* b_head = (const float*)d_in[6];
    const float* W_out  = (const float*)d_in[7];
    const float* b_out  = (const float*)d_in[8];
    float* out = (float*)d_out;

    k_zero<<<2048, 256>>>();
    k_trA<<<dim3(32, 64), dim3(32, 8)>>>(W_ih, W_hh);
    k_trH<<<dim3(16, 17), dim3(32, 8)>>>(W_head);
    k_trO<<<dim3(24, 8),  dim3(32, 8)>>>(W_out);
    k_steps<<<NBLK, 256>>>(x, b_ih, b_hh, b_head);
    k_out<<<dim3(32, 4), 256>>>(b_out, out);
    k_final<<<2048, 256>>>(out);
}